// round 11
// baseline (speedup 1.0000x reference)
#include <cuda_runtime.h>
#include <cstdint>

#define BATCH 16384
typedef unsigned long long u64;

__device__ __forceinline__ float relu(float x) { return x > 0.f ? x : 0.f; }
__device__ __forceinline__ u64 dup2(float x) {
    u64 r; asm("mov.b64 %0, {%1,%1};" : "=l"(r) : "f"(x)); return r;
}
__device__ __forceinline__ u64 pack2(float lo, float hi) {
    u64 r; asm("mov.b64 %0, {%1,%2};" : "=l"(r) : "f"(lo), "f"(hi)); return r;
}
__device__ __forceinline__ void fma2(u64& d, u64 a, u64 b) {
    asm("fma.rn.f32x2 %0, %1, %2, %0;" : "+l"(d) : "l"(a), "l"(b));
}
__device__ __forceinline__ float2 u2f(u64 v) {
    float2 r; asm("mov.b64 {%0,%1}, %2;" : "=f"(r.x), "=f"(r.y) : "l"(v)); return r;
}

// shared layout (float offsets); 8 samples per block
//   0     sb     8*1572   board planes: per sample 3 planes x (26 rows x 20 cols),
//                         sample stride 1572 (=4 mod 32 -> per-sample bank skew)
//   12576 wc1p   600      conv1 w packed [tap(75)][oc0..5,pad2]
//   13176 w2s    2400     conv2 w [ci][dy][dx][oc0..15]
//   15576 w3s    3072     conv3 w [ci*3+dy][oc0..63]
//   18648 l1s    2048     lfc1^T [k(64)][j(32)]
//   20696 was    1024     folded attention W [k(32)][i(32)]
//   21720 fws    256      fc_w^T [k(8)][j(32)]
//   21976 bias   184      c2b[0:16) c3b[16:80) l1b[80:112) fcb[112:144) batt[144:176) b1[176:182)
//   22160 p1     8*396    pooled conv1 output per sample
//   total 25328 floats = 101312 B  (2 blocks/SM)
// aliases: fold temps (2144) overlay p1; tail bufs (8*336) overlay sb
#define SMEM_FLOATS 25328

__global__ __launch_bounds__(256) void k_fused(
    const int* __restrict__ t, const int* __restrict__ ptab,
    const float* __restrict__ w1, const float* __restrict__ b1,
    const float* __restrict__ w2, const float* __restrict__ c2b,
    const float* __restrict__ w3, const float* __restrict__ c3b,
    const float* __restrict__ lfc1, const float* __restrict__ l1b,
    const float* __restrict__ fcw, const float* __restrict__ fcb,
    const float* __restrict__ ipw, const float* __restrict__ ipb,
    const float* __restrict__ outw, const float* __restrict__ outb,
    float* __restrict__ out, float* __restrict__ boardOut, int writeBoard) {
    extern __shared__ float sm[];
    float* sb   = sm;
    float* wc1p = sm + 12576;
    float* w2s  = sm + 13176;
    float* w3s  = sm + 15576;
    float* l1s  = sm + 18648;
    float* was  = sm + 20696;
    float* fws  = sm + 21720;
    float* bias = sm + 21976;
    float* p1   = sm + 22160;
    float* ow_s = p1;            // 1056 (33-stride padded)
    float* iv_s = p1 + 1056;     // 1024
    float* ib_s = p1 + 2080;     // 32
    float* ob_s = p1 + 2112;     // 32
    float* tbuf = sb;            // tail buffers alias boards (dead after conv1)

    int tid = threadIdx.x;
    int b0 = blockIdx.x * 8;

    // ---------- step 1: weight staging ----------
    for (int i = tid; i < 600; i += 256) {
        int oc = i % 8; int tap = i / 8;
        int dx = tap % 5, dy = (tap / 5) % 5, ch = tap / 25;
        wc1p[i] = (oc < 6) ? w1[((oc * 3 + ch) * 5 + dy) * 5 + dx] : 0.f;
    }
    for (int i = tid; i < 2400; i += 256) {
        int oc = i % 16; int r = i / 16; int dx = r % 5; r /= 5; int dy = r % 5; int ci = r / 5;
        w2s[i] = w2[((oc * 6 + ci) * 5 + dy) * 5 + dx];
    }
    for (int i = tid; i < 3072; i += 256) {
        int o = i % 64; int r = i / 64; int dy = r % 3; int ci = r / 3;
        w3s[i] = w3[(o * 16 + ci) * 3 + dy];
    }
    for (int i = tid; i < 2048; i += 256) { int j = i % 32, k = i / 32; l1s[i] = lfc1[j * 64 + k]; }
    for (int i = tid; i < 256; i += 256) { int j = i % 32, k = i / 32; fws[i] = fcw[j * 8 + k]; }
    for (int i = tid; i < 1024; i += 256) {
        ow_s[(i / 32) * 33 + (i % 32)] = outw[i];
        iv_s[i] = ipw[(64 + (i / 32)) * 32 + (i % 32)];
    }
    for (int i = tid; i < 32; i += 256) {
        ib_s[i] = ipb[64 + i];
        ob_s[i] = outb[i];
        bias[80 + i] = l1b[i];
        bias[112 + i] = fcb[i];
    }
    for (int i = tid; i < 16; i += 256) bias[i] = c2b[i];
    for (int i = tid; i < 64; i += 256) bias[16 + i] = c3b[i];
    if (tid < 6) bias[176 + tid] = b1[tid];
    for (int i = tid; i < 12576 / 4; i += 256) ((float4*)sb)[i] = make_float4(0.f, 0.f, 0.f, 0.f);
    __syncthreads();

    // ---------- step 2: board fill (warp per sample) + attention fold ----------
    int wId = tid >> 5;
    int lane = tid & 31;
    {
        const int* trow = t + (size_t)(b0 + wId) * 232;
        float* S = sb + wId * 1572;
        for (int i = lane; i < 210; i += 32) {
            int r = i / 10, c = i % 10;
            S[(r + 2) * 20 + (c + 3)] = (float)trow[22 + i];
        }
        for (int i = lane; i < 168; i += 32) {
            int ch = i / 56, j = i % 56;
            int r, c;
            if (j < 22) { r = j; c = 0; }
            else if (j < 44) { r = j - 22; c = 11; }
            else { r = 21; c = j - 44; }
            S[ch * 520 + (r + 2) * 20 + (c + 2)] = 1.0f;
        }
        if (lane == 0) {
            int t1 = trow[1], t2 = trow[2], t3 = trow[3], t4 = trow[4], t8 = trow[8];
            const int* p = ptab + t8 * 64 + t4 * 16;
            int sel[4]; int cnt = 0;
            for (int i = 0; i < 16 && cnt < 4; i++) if (p[i] != 0) sel[cnt++] = i;
            for (int i = 0; i < 16 && cnt < 4; i++) if (p[i] == 0) sel[cnt++] = i;
            for (int s = 0; s < 4; s++) {
                int cy = sel[s] >> 2, cx = sel[s] & 3;
                int x = cx + t1 - 2;
                int y = cy + t2;
                int ny = y + t3;
                if (y >= 0 && ny >= 0 && x >= 0 && x < 10) {
                    if (y < 21)  S[1 * 520 + (y + 2) * 20 + (x + 3)] = 1.0f;
                    if (ny < 21) S[2 * 520 + (ny + 2) * 20 + (x + 3)] = 1.0f;
                }
            }
        }
    }
    // W_att[i][j] = sum_k outw[i,k] * vw[k,j]; stored was[j*32+i]
    for (int i = tid; i < 1024; i += 256) {
        int ii = i & 31, j = i >> 5;
        float s = 0.f;
        #pragma unroll
        for (int k = 0; k < 32; k++) s += ow_s[ii * 33 + k] * iv_s[k * 32 + j];
        was[j * 32 + ii] = s;
    }
    if (tid < 32) {
        float s = ob_s[tid];
        #pragma unroll
        for (int k = 0; k < 32; k++) s += ow_s[tid * 33 + k] * ib_s[k];
        bias[144 + tid] = s;
    }
    __syncthreads();

    // ---------- step 3: board write + conv1/relu/pool (2 pooled positions per thread) ----------
    if (writeBoard) {
        const float* S = sb + wId * 1572;
        float4* obp = (float4*)(boardOut + (size_t)(b0 + wId) * 792);
        for (int i = lane; i < 198; i += 32) {
            int e = i * 4;
            int ch = e / 264, rr = (e % 264) / 12, c0 = e % 12;
            const float* q = S + ch * 520 + (rr + 2) * 20 + (c0 + 2);
            obp[i] = make_float4(q[0], q[1], q[2], q[3]);
        }
    }

    for (int u = tid; u < 264; u += 256) {
        int g2 = u & 7, pos = u >> 3;            // pos 0..32
        int py = pos / 3, pxp = pos % 3;          // py 0..10, px pair (2pxp, 2pxp+1)
        const float* P = sb + g2 * 1572;
        int x0 = 4 * pxp;

        u64 aT0[3] = {0,0,0}, aT1[3] = {0,0,0}, aT2[3] = {0,0,0}, aT3[3] = {0,0,0};
        u64 aB0[3] = {0,0,0}, aB1[3] = {0,0,0}, aB2[3] = {0,0,0}, aB3[3] = {0,0,0};

        #pragma unroll
        for (int ch = 0; ch < 3; ch++) {
            const float* plane = P + ch * 520;
            #pragma unroll
            for (int dy = 0; dy < 5; dy++) {
                const float* rA = plane + (2 * py + dy) * 20 + x0;
                float4 a0 = *(const float4*)rA;
                float4 a1 = *(const float4*)(rA + 4);
                float4 c0 = *(const float4*)(rA + 20);
                float4 c1 = *(const float4*)(rA + 24);
                u64 da[8] = {dup2(a0.x), dup2(a0.y), dup2(a0.z), dup2(a0.w),
                             dup2(a1.x), dup2(a1.y), dup2(a1.z), dup2(a1.w)};
                u64 db[8] = {dup2(c0.x), dup2(c0.y), dup2(c0.z), dup2(c0.w),
                             dup2(c1.x), dup2(c1.y), dup2(c1.z), dup2(c1.w)};
                const float* wb = wc1p + (ch * 5 + dy) * 40;
                #pragma unroll
                for (int dx = 0; dx < 5; dx++) {
                    ulonglong2 wq = *(const ulonglong2*)(wb + dx * 8);
                    u64 w2w = *(const u64*)(wb + dx * 8 + 4);
                    fma2(aT0[0], wq.x, da[dx + 0]); fma2(aT0[1], wq.y, da[dx + 0]); fma2(aT0[2], w2w, da[dx + 0]);
                    fma2(aT1[0], wq.x, da[dx + 1]); fma2(aT1[1], wq.y, da[dx + 1]); fma2(aT1[2], w2w, da[dx + 1]);
                    fma2(aT2[0], wq.x, da[dx + 2]); fma2(aT2[1], wq.y, da[dx + 2]); fma2(aT2[2], w2w, da[dx + 2]);
                    fma2(aT3[0], wq.x, da[dx + 3]); fma2(aT3[1], wq.y, da[dx + 3]); fma2(aT3[2], w2w, da[dx + 3]);
                    fma2(aB0[0], wq.x, db[dx + 0]); fma2(aB0[1], wq.y, db[dx + 0]); fma2(aB0[2], w2w, db[dx + 0]);
                    fma2(aB1[0], wq.x, db[dx + 1]); fma2(aB1[1], wq.y, db[dx + 1]); fma2(aB1[2], w2w, db[dx + 1]);
                    fma2(aB2[0], wq.x, db[dx + 2]); fma2(aB2[1], wq.y, db[dx + 2]); fma2(aB2[2], w2w, db[dx + 2]);
                    fma2(aB3[0], wq.x, db[dx + 3]); fma2(aB3[1], wq.y, db[dx + 3]); fma2(aB3[2], w2w, db[dx + 3]);
                }
            }
        }

        float* dst = p1 + g2 * 396 + py * 6 + 2 * pxp;
        #pragma unroll
        for (int k = 0; k < 3; k++) {
            float bb0 = bias[176 + 2 * k], bb1 = bias[176 + 2 * k + 1];
            float2 T0 = u2f(aT0[k]), T1 = u2f(aT1[k]), T2 = u2f(aT2[k]), T3 = u2f(aT3[k]);
            float2 B0 = u2f(aB0[k]), B1 = u2f(aB1[k]), B2 = u2f(aB2[k]), B3 = u2f(aB3[k]);
            dst[(2 * k) * 66]         = 0.25f * (relu(T0.x + bb0) + relu(T1.x + bb0) + relu(B0.x + bb0) + relu(B1.x + bb0));
            dst[(2 * k) * 66 + 1]     = 0.25f * (relu(T2.x + bb0) + relu(T3.x + bb0) + relu(B2.x + bb0) + relu(B3.x + bb0));
            dst[(2 * k + 1) * 66]     = 0.25f * (relu(T0.y + bb1) + relu(T1.y + bb1) + relu(B0.y + bb1) + relu(B1.y + bb1));
            dst[(2 * k + 1) * 66 + 1] = 0.25f * (relu(T2.y + bb1) + relu(T3.y + bb1) + relu(B2.y + bb1) + relu(B3.y + bb1));
        }
    }
    __syncthreads();

    // ---------- step 4: tail (8 warps, one sample each) ----------
    {
        int b = b0 + wId;
        float* p1s = p1 + wId * 396;
        float* c2s = tbuf + wId * 336;
        float* p2s = c2s + 192;
        float* x64s = p2s + 48;
        float* b2s = x64s + 64;

        // conv2 (FMA2): lane -> oc-pair op(0..7), xx(0..1), y-half yh(0..1)
        {
            int op = lane >> 2;
            int xx = (lane >> 1) & 1;
            int yh = lane & 1;
            int y0 = 3 * yh;
            u64 acc0 = pack2(bias[2 * op], bias[2 * op + 1]);
            u64 acc1 = acc0, acc2 = acc0;
            for (int ci = 0; ci < 6; ci++) {
                #pragma unroll
                for (int dx = 0; dx < 5; dx++) {
                    const float* base = p1s + ci * 66 + xx + dx + y0 * 6;
                    u64 dc[7];
                    #pragma unroll
                    for (int j = 0; j < 7; j++) dc[j] = dup2(base[j * 6]);
                    const float* wb = w2s + ((ci * 5) * 5 + dx) * 16 + 2 * op;
                    #pragma unroll
                    for (int dy = 0; dy < 5; dy++) {
                        u64 wv = *(const u64*)(wb + dy * 80);
                        fma2(acc0, wv, dc[dy]);
                        fma2(acc1, wv, dc[dy + 1]);
                        fma2(acc2, wv, dc[dy + 2]);
                    }
                }
            }
            float2 v0 = u2f(acc0), v1 = u2f(acc1), v2 = u2f(acc2);
            int r0 = (2 * op) * 12 + y0 * 2 + xx;
            int r1 = (2 * op + 1) * 12 + y0 * 2 + xx;
            c2s[r0]     = relu(v0.x); c2s[r1]     = relu(v0.y);
            c2s[r0 + 2] = relu(v1.x); c2s[r1 + 2] = relu(v1.y);
            c2s[r0 + 4] = relu(v2.x); c2s[r1 + 4] = relu(v2.y);
        }
        __syncwarp();

        for (int i = lane; i < 48; i += 32) {
            int base = (i / 3) * 12 + (i % 3) * 4;
            p2s[i] = 0.25f * (c2s[base] + c2s[base + 1] + c2s[base + 2] + c2s[base + 3]);
        }
        __syncwarp();

        {
            float accA = bias[16 + lane];
            float accB = bias[16 + lane + 32];
            #pragma unroll
            for (int k = 0; k < 48; k++) {
                float iv = p2s[k];
                accA += iv * w3s[k * 64 + lane];
                accB += iv * w3s[k * 64 + lane + 32];
            }
            x64s[lane] = relu(accA);
            x64s[lane + 32] = relu(accB);
        }
        __syncwarp();

        {
            float acc = bias[80 + lane];
            #pragma unroll
            for (int i = 0; i < 64; i++) acc += x64s[i] * l1s[i * 32 + lane];
            float v = relu(acc);
            b2s[lane] = v;
            out[(size_t)b * 96 + 64 + lane] = v;
        }
        __syncwarp();

        {
            float acc = bias[144 + lane];
            #pragma unroll
            for (int k = 0; k < 32; k++) acc += b2s[k] * was[k * 32 + lane];
            out[(size_t)b * 96 + 32 + lane] = acc;
        }

        {
            const int* tr2 = t + (size_t)b * 232;
            float tv = (lane < 8) ? (float)tr2[lane] : 0.f;
            float acc = bias[112 + lane];
            #pragma unroll
            for (int i = 0; i < 8; i++) {
                float ti = __shfl_sync(0xffffffffu, tv, i);
                acc += ti * fws[i * 32 + lane];
            }
            out[(size_t)b * 96 + lane] = relu(acc);
        }
    }
}

// ---------------- launch ----------------
extern "C" void kernel_launch(void* const* d_in, const int* in_sizes, int n_in,
                              void* d_out, int out_size) {
    const int* t = (const int*)d_in[0];
    const int* ptab = (const int*)d_in[1];
    const float* w1 = (const float*)d_in[2];
    const float* b1 = (const float*)d_in[3];
    const float* w2 = (const float*)d_in[4];
    const float* b2 = (const float*)d_in[5];
    const float* w3 = (const float*)d_in[6];
    const float* b3 = (const float*)d_in[7];
    const float* lfc1 = (const float*)d_in[8];
    const float* l1b = (const float*)d_in[9];
    const float* fcw = (const float*)d_in[10];
    const float* fcb = (const float*)d_in[11];
    const float* ipw = (const float*)d_in[13];
    const float* ipb = (const float*)d_in[14];
    const float* outw = (const float*)d_in[15];
    const float* outb = (const float*)d_in[16];
    float* out = (float*)d_out;

    int hasBoard = (out_size >= BATCH * (96 + 792)) ? 1 : 0;
    float* boardOut = out + (size_t)BATCH * 96;

    static const int kSmem = SMEM_FLOATS * 4;
    cudaFuncSetAttribute(k_fused, cudaFuncAttributeMaxDynamicSharedMemorySize, kSmem);
    k_fused<<<BATCH / 8, 256, kSmem>>>(t, ptab, w1, b1, w2, b2, w3, b3, lfc1, l1b,
                                       fcw, fcb, ipw, ipb, outw, outb,
                                       out, boardOut, hasBoard);
}